// round 4
// baseline (speedup 1.0000x reference)
#include <cuda_runtime.h>
#include <cuda_bf16.h>
#include <math.h>
#include <stdint.h>

// ---------------- problem constants ----------------
#define TOK   16384            // B*N = 4*4096
#define DIMC  1024
#define H3    3072             // 3*C
#define HID   2048
#define NB    4
#define NSEQ  4096
#define NHEAD 16
#define HD    64
#define KVCH  8                // kv reduction chunks (512 tokens each)

// ---------------- scratch (device globals; no allocs allowed) ----------------
__device__ float g_xn  [(size_t)TOK * DIMC];   //  67 MB  xn / xn2
__device__ float g_qkv [(size_t)TOK * H3];     // 201 MB  qkv (phi applied to q,k)
__device__ float g_attn[(size_t)TOK * DIMC];   //  67 MB  attention out (pre-proj)
__device__ float g_hdd [(size_t)TOK * HID];    // 134 MB  MLP hidden
__device__ float g_kv  [NB * NHEAD * HD * HD]; //   1 MB
__device__ float g_ksum[NB * NHEAD * HD];
__device__ float g_kvp [KVCH * NB * NHEAD * HD * HD];  // 8 MB partials (deterministic)
__device__ float g_ksump[KVCH * NB * NHEAD * HD];

// ---------------- helpers ----------------
__device__ __forceinline__ uint32_t f2tf32(float f) {
    uint32_t o;
    asm("cvt.rna.tf32.f32 %0, %1;" : "=r"(o) : "f"(f));
    return o;
}
__device__ __forceinline__ float tf(float f) { return __uint_as_float(f2tf32(f)); }

__device__ __forceinline__ void mma_tf32(float c[4], const uint32_t a[4], const uint32_t b[2]) {
    asm("mma.sync.aligned.m16n8k8.row.col.f32.tf32.tf32.f32 "
        "{%0,%1,%2,%3}, {%4,%5,%6,%7}, {%8,%9}, {%0,%1,%2,%3};"
        : "+f"(c[0]), "+f"(c[1]), "+f"(c[2]), "+f"(c[3])
        : "r"(a[0]), "r"(a[1]), "r"(a[2]), "r"(a[3]), "r"(b[0]), "r"(b[1]));
}

// ---------------- RMSNorm:  y = x * scale * (sqrt(C)+eps)/||x|| ----------------
__global__ void rmsnorm_kernel(const float* __restrict__ x,
                               const float* __restrict__ scale,
                               float* __restrict__ y) {
    int row = blockIdx.x, tid = threadIdx.x;
    const float4* xr = (const float4*)(x + (size_t)row * DIMC);
    float4 v = xr[tid];                               // 256 thr * 4 = 1024
    float s = v.x * v.x + v.y * v.y + v.z * v.z + v.w * v.w;
#pragma unroll
    for (int o = 16; o; o >>= 1) s += __shfl_xor_sync(0xffffffffu, s, o);
    __shared__ float ws[8];
    __shared__ float inv;
    if ((tid & 31) == 0) ws[tid >> 5] = s;
    __syncthreads();
    if (tid == 0) {
        float t = 0.f;
#pragma unroll
        for (int i = 0; i < 8; i++) t += ws[i];
        inv = (32.0f + 1e-6f) / sqrtf(t);
    }
    __syncthreads();
    float4 sc = ((const float4*)scale)[tid];
    float iv = inv;
    float4 o;
    o.x = v.x * sc.x * iv; o.y = v.y * sc.y * iv;
    o.z = v.z * sc.z * iv; o.w = v.w * sc.w * iv;
    ((float4*)(y + (size_t)row * DIMC))[tid] = o;
}

// ---------------- TF32 tensor-core GEMM:  C[M,Nn] = A[M,K] * Bw[Nn,K]^T ----------------
// EPI 0: qkv     -> phi(t)=exp(-0.5 t^2) for n < 2*DIMC (q,k), identity for v
// EPI 1: resid   -> C = resid + gamma[n]*(acc + bias[n])
// EPI 2: gelu    -> C = gelu_exact(acc + bias[n])
template <int EPI>
__device__ __forceinline__ float epi_apply(float acc, int m, int n, int Nn,
                                           const float* bias, const float* resid,
                                           const float* gamma) {
    if (EPI == 0) {
        return (n < 2 * DIMC) ? expf(-0.5f * acc * acc) : acc;
    } else if (EPI == 1) {
        return resid[(size_t)m * Nn + n] + gamma[n] * (acc + bias[n]);
    } else {
        float v = acc + bias[n];
        return 0.5f * v * (1.0f + erff(v * 0.70710678118654752f));
    }
}

template <int EPI>
__global__ void __launch_bounds__(256)
gemm_kernel(const float* __restrict__ A, const float* __restrict__ Bw,
            float* __restrict__ C, int M, int Nn, int K,
            const float* __restrict__ bias, const float* __restrict__ resid,
            const float* __restrict__ gamma) {
    __shared__ float As[2][128][20];   // BK=16, pad->20 (conflict-free frag loads)
    __shared__ float Bs[2][128][20];

    const int tid  = threadIdx.x;
    const int lane = tid & 31, warp = tid >> 5;
    const int wm = warp & 1, wn = warp >> 1;      // warps: 2 along M, 4 along N
    const int gp = lane >> 2, t4 = lane & 3;
    const int lrow = tid >> 2, lcol = (tid & 3) << 2;

    const float* Ab = A  + (size_t)(blockIdx.y * 128 + lrow) * K + lcol;
    const float* Bb = Bw + (size_t)(blockIdx.x * 128 + lrow) * K + lcol;
    const size_t rstep = (size_t)64 * K;

    float acc[4][4][4];
#pragma unroll
    for (int i = 0; i < 4; i++)
#pragma unroll
        for (int j = 0; j < 4; j++)
#pragma unroll
            for (int r = 0; r < 4; r++) acc[i][j][r] = 0.f;

    const int KT = K >> 4;
    float4 ra0, ra1, rb0, rb1;

    // preload tile 0
    ra0 = *(const float4*)(Ab);
    ra1 = *(const float4*)(Ab + rstep);
    rb0 = *(const float4*)(Bb);
    rb1 = *(const float4*)(Bb + rstep);
    {
        float4 c0 = make_float4(tf(ra0.x), tf(ra0.y), tf(ra0.z), tf(ra0.w));
        float4 c1 = make_float4(tf(ra1.x), tf(ra1.y), tf(ra1.z), tf(ra1.w));
        float4 c2 = make_float4(tf(rb0.x), tf(rb0.y), tf(rb0.z), tf(rb0.w));
        float4 c3 = make_float4(tf(rb1.x), tf(rb1.y), tf(rb1.z), tf(rb1.w));
        *(float4*)&As[0][lrow][lcol]      = c0;
        *(float4*)&As[0][lrow + 64][lcol] = c1;
        *(float4*)&Bs[0][lrow][lcol]      = c2;
        *(float4*)&Bs[0][lrow + 64][lcol] = c3;
    }
    __syncthreads();

    for (int kt = 0; kt < KT; kt++) {
        const int cur = kt & 1;
        if (kt + 1 < KT) {  // prefetch next tile into registers (overlaps mma)
            const float* Ak = Ab + (kt + 1) * 16;
            const float* Bk = Bb + (kt + 1) * 16;
            ra0 = *(const float4*)(Ak);
            ra1 = *(const float4*)(Ak + rstep);
            rb0 = *(const float4*)(Bk);
            rb1 = *(const float4*)(Bk + rstep);
        }
#pragma unroll
        for (int ks = 0; ks < 2; ks++) {
            uint32_t af[4][4], bf[4][2];
#pragma unroll
            for (int mi = 0; mi < 4; mi++) {
                int r = wm * 64 + mi * 16 + gp;
                af[mi][0] = __float_as_uint(As[cur][r][ks * 8 + t4]);
                af[mi][1] = __float_as_uint(As[cur][r + 8][ks * 8 + t4]);
                af[mi][2] = __float_as_uint(As[cur][r][ks * 8 + t4 + 4]);
                af[mi][3] = __float_as_uint(As[cur][r + 8][ks * 8 + t4 + 4]);
            }
#pragma unroll
            for (int ni = 0; ni < 4; ni++) {
                int c = wn * 32 + ni * 8 + gp;
                bf[ni][0] = __float_as_uint(Bs[cur][c][ks * 8 + t4]);
                bf[ni][1] = __float_as_uint(Bs[cur][c][ks * 8 + t4 + 4]);
            }
#pragma unroll
            for (int mi = 0; mi < 4; mi++)
#pragma unroll
                for (int ni = 0; ni < 4; ni++)
                    mma_tf32(acc[mi][ni], af[mi], bf[ni]);
        }
        if (kt + 1 < KT) {
            const int nxt = cur ^ 1;
            float4 c0 = make_float4(tf(ra0.x), tf(ra0.y), tf(ra0.z), tf(ra0.w));
            float4 c1 = make_float4(tf(ra1.x), tf(ra1.y), tf(ra1.z), tf(ra1.w));
            float4 c2 = make_float4(tf(rb0.x), tf(rb0.y), tf(rb0.z), tf(rb0.w));
            float4 c3 = make_float4(tf(rb1.x), tf(rb1.y), tf(rb1.z), tf(rb1.w));
            *(float4*)&As[nxt][lrow][lcol]      = c0;
            *(float4*)&As[nxt][lrow + 64][lcol] = c1;
            *(float4*)&Bs[nxt][lrow][lcol]      = c2;
            *(float4*)&Bs[nxt][lrow + 64][lcol] = c3;
            __syncthreads();
        }
    }

    // epilogue
#pragma unroll
    for (int mi = 0; mi < 4; mi++) {
        int m = blockIdx.y * 128 + wm * 64 + mi * 16 + gp;
#pragma unroll
        for (int ni = 0; ni < 4; ni++) {
            int n = blockIdx.x * 128 + wn * 32 + ni * 8 + (t4 << 1);
            float* Cp = C + (size_t)m * Nn + n;
            Cp[0] = epi_apply<EPI>(acc[mi][ni][0], m, n,     Nn, bias, resid, gamma);
            Cp[1] = epi_apply<EPI>(acc[mi][ni][1], m, n + 1, Nn, bias, resid, gamma);
            float* Cq = Cp + (size_t)8 * Nn;
            Cq[0] = epi_apply<EPI>(acc[mi][ni][2], m + 8, n,     Nn, bias, resid, gamma);
            Cq[1] = epi_apply<EPI>(acc[mi][ni][3], m + 8, n + 1, Nn, bias, resid, gamma);
        }
    }
}

// ---------------- kv partials: kvp[ch][bh][d][e] = sum_{n in ch} k[n,d] v[n,e] ----------------
// grid (64 bh, 8 chunks of 512 tokens), 256 threads. Plain stores (deterministic).
__global__ void __launch_bounds__(256) kv_kernel() {
    const int bh = blockIdx.x, h = bh & 15, b = bh >> 4;
    const int ch = blockIdx.y;
    const int tid = threadIdx.x;
    const int d = tid >> 2, e0 = (tid & 3) << 4;
    __shared__ float k_s[64][64], v_s[64][64];

    float acc[16];
#pragma unroll
    for (int j = 0; j < 16; j++) acc[j] = 0.f;
    float ks = 0.f;

    for (int sub = 0; sub < 8; sub++) {
        const int tbase = b * NSEQ + (ch * 8 + sub) * 64;
        __syncthreads();
        for (int i = tid; i < 64 * 64; i += 256) {
            int t = i >> 6, dd = i & 63;
            size_t off = (size_t)(tbase + t) * H3 + h * HD + dd;
            k_s[t][dd] = g_qkv[off + DIMC];       // phi(k), applied in GEMM1 epilogue
            v_s[t][dd] = g_qkv[off + 2 * DIMC];   // v
        }
        __syncthreads();
        for (int t = 0; t < 64; t++) {
            float kd = k_s[t][d];
            ks += kd;
#pragma unroll
            for (int j = 0; j < 16; j++) acc[j] += kd * v_s[t][e0 + j];
        }
    }

    float* kvp = g_kvp + ((size_t)ch * 64 + bh) * (HD * HD) + d * HD + e0;
#pragma unroll
    for (int j = 0; j < 16; j++) kvp[j] = acc[j];
    if ((tid & 3) == 0) g_ksump[((size_t)ch * 64 + bh) * HD + d] = ks;
}

// ---------------- reduce partials (fixed order -> deterministic) ----------------
// grid 64 (bh), 256 threads; each thread reduces 16 kv elems over 8 chunks.
__global__ void __launch_bounds__(256) kv_reduce_kernel() {
    const int bh = blockIdx.x, tid = threadIdx.x;
    const int base = tid * 16;
    float acc[16];
#pragma unroll
    for (int j = 0; j < 16; j++) acc[j] = 0.f;
#pragma unroll
    for (int c = 0; c < KVCH; c++) {
        const float* p = g_kvp + ((size_t)c * 64 + bh) * (HD * HD) + base;
#pragma unroll
        for (int j = 0; j < 16; j++) acc[j] += p[j];
    }
    float* o = g_kv + (size_t)bh * (HD * HD) + base;
#pragma unroll
    for (int j = 0; j < 16; j++) o[j] = acc[j];
    if (tid < HD) {
        float s = 0.f;
#pragma unroll
        for (int c = 0; c < KVCH; c++) s += g_ksump[((size_t)c * 64 + bh) * HD + tid];
        g_ksum[bh * HD + tid] = s;
    }
}

// ---------------- out[n,e] = z * sum_d q[n,d] kv[d,e],  z = 1/(q.ksum + 1e-6) ----------------
// grid (64 bh, 64 chunks of 64 tokens), 256 threads
__global__ void __launch_bounds__(256) out_kernel() {
    const int bh = blockIdx.x, h = bh & 15, b = bh >> 4;
    const int tbase = b * NSEQ + blockIdx.y * 64;
    __shared__ float q_s[64][64], kv_s[64][64];
    __shared__ float z_s[64], ksum_s[64];
    const int tid = threadIdx.x;
    for (int i = tid; i < 64 * 64; i += 256) {
        int t = i >> 6, d = i & 63;
        q_s[t][d]  = g_qkv[(size_t)(tbase + t) * H3 + h * HD + d];  // phi(q)
        kv_s[t][d] = g_kv[(size_t)bh * (HD * HD) + i];
    }
    if (tid < 64) ksum_s[tid] = g_ksum[bh * HD + tid];
    __syncthreads();
    if (tid < 64) {
        float dot = 0.f;
#pragma unroll
        for (int d = 0; d < 64; d++) dot += q_s[tid][d] * ksum_s[d];
        z_s[tid] = 1.0f / (dot + 1e-6f);
    }
    __syncthreads();
    const int e = tid & 63, t0 = tid >> 6;
#pragma unroll
    for (int tt = 0; tt < 16; tt++) {
        int t = t0 + tt * 4;
        float s = 0.f;
#pragma unroll
        for (int d = 0; d < 64; d++) s += q_s[t][d] * kv_s[d][e];
        g_attn[(size_t)(tbase + t) * DIMC + h * HD + e] = z_s[t] * s;
    }
}

// ---------------- launcher ----------------
extern "C" void kernel_launch(void* const* d_in, const int* in_sizes, int n_in,
                              void* d_out, int out_size) {
    const float* x       = (const float*)d_in[0];
    const float* scale1  = (const float*)d_in[1];
    const float* scale2  = (const float*)d_in[2];
    const float* gamma   = (const float*)d_in[3];
    const float* qkv_w   = (const float*)d_in[4];
    const float* proj_w  = (const float*)d_in[5];
    const float* proj_b  = (const float*)d_in[6];
    const float* conv1_w = (const float*)d_in[7];
    const float* conv1_b = (const float*)d_in[8];
    const float* conv2_w = (const float*)d_in[9];
    const float* conv2_b = (const float*)d_in[10];
    float* out = (float*)d_out;

    float *xn, *qkv, *attn, *hdd;
    cudaGetSymbolAddress((void**)&xn,   g_xn);
    cudaGetSymbolAddress((void**)&qkv,  g_qkv);
    cudaGetSymbolAddress((void**)&attn, g_attn);
    cudaGetSymbolAddress((void**)&hdd,  g_hdd);

    // 1. xn = rmsnorm(x, scale1)
    rmsnorm_kernel<<<TOK, 256>>>(x, scale1, xn);
    // 2. qkv = xn @ qkv_w^T ; phi applied to q,k in epilogue
    gemm_kernel<0><<<dim3(H3 / 128, TOK / 128), 256>>>(
        xn, qkv_w, qkv, TOK, H3, DIMC, nullptr, nullptr, nullptr);
    // 3. kv partials (deterministic, no atomics) + 4. fixed-order reduce
    kv_kernel<<<dim3(NB * NHEAD, KVCH), 256>>>();
    kv_reduce_kernel<<<NB * NHEAD, 256>>>();
    // 5. attn_out = z * (q @ kv)
    out_kernel<<<dim3(NB * NHEAD, NSEQ / 64), 256>>>();
    // 6. x2 = x + gamma * (attn_out @ proj_w^T + proj_b)   -> d_out
    gemm_kernel<1><<<dim3(DIMC / 128, TOK / 128), 256>>>(
        attn, proj_w, out, TOK, DIMC, DIMC, proj_b, x, gamma);
    // 7. xn2 = rmsnorm(x2, scale2)
    rmsnorm_kernel<<<TOK, 256>>>(out, scale2, xn);
    // 8. hdd = gelu(xn2 @ conv1_w^T + conv1_b)
    gemm_kernel<2><<<dim3(HID / 128, TOK / 128), 256>>>(
        xn, conv1_w, hdd, TOK, HID, DIMC, conv1_b, nullptr, nullptr);
    // 9. out = x2 + gamma * (hdd @ conv2_w^T + conv2_b)
    gemm_kernel<1><<<dim3(DIMC / 128, TOK / 128), 256>>>(
        hdd, conv2_w, out, TOK, DIMC, HID, conv2_b, out, gamma);
}

// round 16
// speedup vs baseline: 1.2713x; 1.2713x over previous
#include <cuda_runtime.h>
#include <cuda_bf16.h>
#include <math.h>
#include <stdint.h>

// ---------------- problem constants ----------------
#define TOK   16384            // B*N = 4*4096
#define DIMC  1024
#define H3    3072             // 3*C
#define HID   2048
#define NB    4
#define NSEQ  4096
#define NHEAD 16
#define HD    64
#define KVCH  8                // kv reduction chunks (512 tokens each)

// GEMM tiling
#define BK      32
#define STAGES  3
#define ASTRIDE 36                         // 32 + 4 pad (conflict-free)
#define TILE_F  (128 * ASTRIDE)            // floats per tile buffer
#define STG_F   (2 * TILE_F)               // A + B per stage
#define SMEM_BYTES (STAGES * STG_F * 4)    // 110592 B

// ---------------- scratch (device globals; no allocs allowed) ----------------
__device__ float g_xn  [(size_t)TOK * DIMC];   //  67 MB  xn / xn2
__device__ float g_qkv [(size_t)TOK * H3];     // 201 MB  qkv (phi applied to q,k)
__device__ float g_attn[(size_t)TOK * DIMC];   //  67 MB  attention out (pre-proj)
__device__ float g_hdd [(size_t)TOK * HID];    // 134 MB  MLP hidden
__device__ float g_kv  [NB * NHEAD * HD * HD]; //   1 MB
__device__ float g_ksum[NB * NHEAD * HD];
__device__ float g_kvp [KVCH * NB * NHEAD * HD * HD];  // 8 MB partials (deterministic)
__device__ float g_ksump[KVCH * NB * NHEAD * HD];

// ---------------- helpers ----------------
__device__ __forceinline__ void mma_tf32(float c[4], const uint32_t a[4], const uint32_t b[2]) {
    asm("mma.sync.aligned.m16n8k8.row.col.f32.tf32.tf32.f32 "
        "{%0,%1,%2,%3}, {%4,%5,%6,%7}, {%8,%9}, {%0,%1,%2,%3};"
        : "+f"(c[0]), "+f"(c[1]), "+f"(c[2]), "+f"(c[3])
        : "r"(a[0]), "r"(a[1]), "r"(a[2]), "r"(a[3]), "r"(b[0]), "r"(b[1]));
}
__device__ __forceinline__ void cpa16(uint32_t dst, const void* src) {
    asm volatile("cp.async.cg.shared.global [%0], [%1], 16;" :: "r"(dst), "l"(src));
}
__device__ __forceinline__ void cpa_commit() {
    asm volatile("cp.async.commit_group;");
}

// ---------------- RMSNorm:  y = x * scale * (sqrt(C)+eps)/||x|| ----------------
__global__ void rmsnorm_kernel(const float* __restrict__ x,
                               const float* __restrict__ scale,
                               float* __restrict__ y) {
    int row = blockIdx.x, tid = threadIdx.x;
    const float4* xr = (const float4*)(x + (size_t)row * DIMC);
    float4 v = xr[tid];                               // 256 thr * 4 = 1024
    float s = v.x * v.x + v.y * v.y + v.z * v.z + v.w * v.w;
#pragma unroll
    for (int o = 16; o; o >>= 1) s += __shfl_xor_sync(0xffffffffu, s, o);
    __shared__ float ws[8];
    __shared__ float inv;
    if ((tid & 31) == 0) ws[tid >> 5] = s;
    __syncthreads();
    if (tid == 0) {
        float t = 0.f;
#pragma unroll
        for (int i = 0; i < 8; i++) t += ws[i];
        inv = (32.0f + 1e-6f) / sqrtf(t);
    }
    __syncthreads();
    float4 sc = ((const float4*)scale)[tid];
    float iv = inv;
    float4 o;
    o.x = v.x * sc.x * iv; o.y = v.y * sc.y * iv;
    o.z = v.z * sc.z * iv; o.w = v.w * sc.w * iv;
    ((float4*)(y + (size_t)row * DIMC))[tid] = o;
}

// ---------------- TF32 tensor-core GEMM (cp.async 3-stage):  C = A * Bw^T ----------------
// EPI 0: qkv   -> phi(t)=exp(-0.5 t^2) for n < 2*DIMC (q,k), identity for v
// EPI 1: resid -> C = resid + gamma[n]*(acc + bias[n])
// EPI 2: gelu  -> C = gelu_exact(acc + bias[n])
template <int EPI>
__device__ __forceinline__ float epi_apply(float acc, int m, int n, int Nn,
                                           const float* bias, const float* resid,
                                           const float* gamma) {
    if (EPI == 0) {
        return (n < 2 * DIMC) ? expf(-0.5f * acc * acc) : acc;
    } else if (EPI == 1) {
        return resid[(size_t)m * Nn + n] + gamma[n] * (acc + bias[n]);
    } else {
        float v = acc + bias[n];
        return 0.5f * v * (1.0f + erff(v * 0.70710678118654752f));
    }
}

template <int EPI>
__global__ void __launch_bounds__(256, 2)
gemm_kernel(const float* __restrict__ A, const float* __restrict__ Bw,
            float* __restrict__ C, int M, int Nn, int K,
            const float* __restrict__ bias, const float* __restrict__ resid,
            const float* __restrict__ gamma) {
    extern __shared__ float sm[];
    const int tid  = threadIdx.x;
    const int lane = tid & 31, warp = tid >> 5;
    const int wm = warp & 1, wn = warp >> 1;      // warps: 2 along M, 4 along N
    const int gp = lane >> 2, t4 = lane & 3;

    const int bm = blockIdx.y * 128, bn = blockIdx.x * 128;

    // cp.async mapping: idx = tid + 256*i (i=0..3); row = idx>>3 (0..127); col = (idx&7)*4
    const int r0 = tid >> 3, cc = (tid & 7) << 2;
    const float* PA = A  + (size_t)(bm + r0) * K + cc;
    const float* PB = Bw + (size_t)(bn + r0) * K + cc;
    const size_t rowstep = (size_t)32 * K;
    const uint32_t su32 = (uint32_t)__cvta_generic_to_shared(sm);

    float acc[4][4][4];
#pragma unroll
    for (int i = 0; i < 4; i++)
#pragma unroll
        for (int j = 0; j < 4; j++)
#pragma unroll
            for (int r = 0; r < 4; r++) acc[i][j][r] = 0.f;

    const int KT = K / BK;

    // ---- prologue: stages 0 .. STAGES-2 ----
#pragma unroll
    for (int s = 0; s < STAGES - 1; s++) {
        const int kcol = s * BK;
        const uint32_t da = su32 + (uint32_t)((s * STG_F + r0 * ASTRIDE + cc) * 4);
        const uint32_t db = da + (uint32_t)(TILE_F * 4);
#pragma unroll
        for (int i = 0; i < 4; i++) {
            cpa16(da + (uint32_t)(i * 32 * ASTRIDE * 4), PA + i * rowstep + kcol);
            cpa16(db + (uint32_t)(i * 32 * ASTRIDE * 4), PB + i * rowstep + kcol);
        }
        cpa_commit();
    }

    for (int kt = 0; kt < KT; kt++) {
        if (kt + 1 < KT) asm volatile("cp.async.wait_group 1;");
        else             asm volatile("cp.async.wait_group 0;");
        __syncthreads();

        // issue stage kt+2 (overlaps with compute below)
        if (kt + STAGES - 1 < KT) {
            const int s = (kt + STAGES - 1) % STAGES;
            const int kcol = (kt + STAGES - 1) * BK;
            const uint32_t da = su32 + (uint32_t)((s * STG_F + r0 * ASTRIDE + cc) * 4);
            const uint32_t db = da + (uint32_t)(TILE_F * 4);
#pragma unroll
            for (int i = 0; i < 4; i++) {
                cpa16(da + (uint32_t)(i * 32 * ASTRIDE * 4), PA + i * rowstep + kcol);
                cpa16(db + (uint32_t)(i * 32 * ASTRIDE * 4), PB + i * rowstep + kcol);
            }
            cpa_commit();
        }

        const float* Asb = sm + (kt % STAGES) * STG_F;
        const float* Bsb = Asb + TILE_F;
#pragma unroll
        for (int ks = 0; ks < 4; ks++) {
            const int c0 = ks * 8 + t4;
            uint32_t af[4][4], bf[4][2];
#pragma unroll
            for (int mi = 0; mi < 4; mi++) {
                const float* ap = Asb + (wm * 64 + mi * 16 + gp) * ASTRIDE + c0;
                af[mi][0] = __float_as_uint(ap[0]);
                af[mi][1] = __float_as_uint(ap[8 * ASTRIDE]);
                af[mi][2] = __float_as_uint(ap[4]);
                af[mi][3] = __float_as_uint(ap[8 * ASTRIDE + 4]);
            }
#pragma unroll
            for (int ni = 0; ni < 4; ni++) {
                const float* bp = Bsb + (wn * 32 + ni * 8 + gp) * ASTRIDE + c0;
                bf[ni][0] = __float_as_uint(bp[0]);
                bf[ni][1] = __float_as_uint(bp[4]);
            }
#pragma unroll
            for (int mi = 0; mi < 4; mi++)
#pragma unroll
                for (int ni = 0; ni < 4; ni++)
                    mma_tf32(acc[mi][ni], af[mi], bf[ni]);
        }
        __syncthreads();
    }

    // epilogue
#pragma unroll
    for (int mi = 0; mi < 4; mi++) {
        int m = bm + wm * 64 + mi * 16 + gp;
#pragma unroll
        for (int ni = 0; ni < 4; ni++) {
            int n = bn + wn * 32 + ni * 8 + (t4 << 1);
            float* Cp = C + (size_t)m * Nn + n;
            Cp[0] = epi_apply<EPI>(acc[mi][ni][0], m, n,     Nn, bias, resid, gamma);
            Cp[1] = epi_apply<EPI>(acc[mi][ni][1], m, n + 1, Nn, bias, resid, gamma);
            float* Cq = Cp + (size_t)8 * Nn;
            Cq[0] = epi_apply<EPI>(acc[mi][ni][2], m + 8, n,     Nn, bias, resid, gamma);
            Cq[1] = epi_apply<EPI>(acc[mi][ni][3], m + 8, n + 1, Nn, bias, resid, gamma);
        }
    }
}

// ---------------- kv partials: kvp[ch][bh][d][e] = sum_{n in ch} k[n,d] v[n,e] ----------------
__global__ void __launch_bounds__(256) kv_kernel() {
    const int bh = blockIdx.x, h = bh & 15, b = bh >> 4;
    const int ch = blockIdx.y;
    const int tid = threadIdx.x;
    const int d = tid >> 2, e0 = (tid & 3) << 4;
    __shared__ float k_s[64][64], v_s[64][64];

    float acc[16];
#pragma unroll
    for (int j = 0; j < 16; j++) acc[j] = 0.f;
    float ks = 0.f;

    for (int sub = 0; sub < 8; sub++) {
        const int tbase = b * NSEQ + (ch * 8 + sub) * 64;
        __syncthreads();
        for (int i = tid; i < 64 * 64; i += 256) {
            int t = i >> 6, dd = i & 63;
            size_t off = (size_t)(tbase + t) * H3 + h * HD + dd;
            k_s[t][dd] = g_qkv[off + DIMC];       // phi(k), applied in GEMM1 epilogue
            v_s[t][dd] = g_qkv[off + 2 * DIMC];   // v
        }
        __syncthreads();
        for (int t = 0; t < 64; t++) {
            float kd = k_s[t][d];
            ks += kd;
#pragma unroll
            for (int j = 0; j < 16; j++) acc[j] += kd * v_s[t][e0 + j];
        }
    }

    float* kvp = g_kvp + ((size_t)ch * 64 + bh) * (HD * HD) + d * HD + e0;
#pragma unroll
    for (int j = 0; j < 16; j++) kvp[j] = acc[j];
    if ((tid & 3) == 0) g_ksump[((size_t)ch * 64 + bh) * HD + d] = ks;
}

// ---------------- reduce partials (fixed order -> deterministic) ----------------
__global__ void __launch_bounds__(256) kv_reduce_kernel() {
    const int bh = blockIdx.x, tid = threadIdx.x;
    const int base = tid * 16;
    float acc[16];
#pragma unroll
    for (int j = 0; j < 16; j++) acc[j] = 0.f;
#pragma unroll
    for (int c = 0; c < KVCH; c++) {
        const float* p = g_kvp + ((size_t)c * 64 + bh) * (HD * HD) + base;
#pragma unroll
        for (int j = 0; j < 16; j++) acc[j] += p[j];
    }
    float* o = g_kv + (size_t)bh * (HD * HD) + base;
#pragma unroll
    for (int j = 0; j < 16; j++) o[j] = acc[j];
    if (tid < HD) {
        float s = 0.f;
#pragma unroll
        for (int c = 0; c < KVCH; c++) s += g_ksump[((size_t)c * 64 + bh) * HD + tid];
        g_ksum[bh * HD + tid] = s;
    }
}

// ---------------- out[n,e] = z * sum_d q[n,d] kv[d,e],  z = 1/(q.ksum + 1e-6) ----------------
__global__ void __launch_bounds__(256) out_kernel() {
    const int bh = blockIdx.x, h = bh & 15, b = bh >> 4;
    const int tbase = b * NSEQ + blockIdx.y * 64;
    __shared__ float q_s[64][64], kv_s[64][64];
    __shared__ float z_s[64], ksum_s[64];
    const int tid = threadIdx.x;
    for (int i = tid; i < 64 * 64; i += 256) {
        int t = i >> 6, d = i & 63;
        q_s[t][d]  = g_qkv[(size_t)(tbase + t) * H3 + h * HD + d];  // phi(q)
        kv_s[t][d] = g_kv[(size_t)bh * (HD * HD) + i];
    }
    if (tid < 64) ksum_s[tid] = g_ksum[bh * HD + tid];
    __syncthreads();
    if (tid < 64) {
        float dot = 0.f;
#pragma unroll
        for (int d = 0; d < 64; d++) dot += q_s[tid][d] * ksum_s[d];
        z_s[tid] = 1.0f / (dot + 1e-6f);
    }
    __syncthreads();
    const int e = tid & 63, t0 = tid >> 6;
#pragma unroll
    for (int tt = 0; tt < 16; tt++) {
        int t = t0 + tt * 4;
        float s = 0.f;
#pragma unroll
        for (int d = 0; d < 64; d++) s += q_s[t][d] * kv_s[d][e];
        g_attn[(size_t)(tbase + t) * DIMC + h * HD + e] = z_s[t] * s;
    }
}

// ---------------- launcher ----------------
extern "C" void kernel_launch(void* const* d_in, const int* in_sizes, int n_in,
                              void* d_out, int out_size) {
    const float* x       = (const float*)d_in[0];
    const float* scale1  = (const float*)d_in[1];
    const float* scale2  = (const float*)d_in[2];
    const float* gamma   = (const float*)d_in[3];
    const float* qkv_w   = (const float*)d_in[4];
    const float* proj_w  = (const float*)d_in[5];
    const float* proj_b  = (const float*)d_in[6];
    const float* conv1_w = (const float*)d_in[7];
    const float* conv1_b = (const float*)d_in[8];
    const float* conv2_w = (const float*)d_in[9];
    const float* conv2_b = (const float*)d_in[10];
    float* out = (float*)d_out;

    float *xn, *qkv, *attn, *hdd;
    cudaGetSymbolAddress((void**)&xn,   g_xn);
    cudaGetSymbolAddress((void**)&qkv,  g_qkv);
    cudaGetSymbolAddress((void**)&attn, g_attn);
    cudaGetSymbolAddress((void**)&hdd,  g_hdd);

    // allow >48KB dynamic smem (idempotent; not an allocation)
    cudaFuncSetAttribute(gemm_kernel<0>, cudaFuncAttributeMaxDynamicSharedMemorySize, SMEM_BYTES);
    cudaFuncSetAttribute(gemm_kernel<1>, cudaFuncAttributeMaxDynamicSharedMemorySize, SMEM_BYTES);
    cudaFuncSetAttribute(gemm_kernel<2>, cudaFuncAttributeMaxDynamicSharedMemorySize, SMEM_BYTES);

    // 1. xn = rmsnorm(x, scale1)
    rmsnorm_kernel<<<TOK, 256>>>(x, scale1, xn);
    // 2. qkv = xn @ qkv_w^T ; phi applied to q,k in epilogue
    gemm_kernel<0><<<dim3(H3 / 128, TOK / 128), 256, SMEM_BYTES>>>(
        xn, qkv_w, qkv, TOK, H3, DIMC, nullptr, nullptr, nullptr);
    // 3. kv partials (deterministic, no atomics) + 4. fixed-order reduce
    kv_kernel<<<dim3(NB * NHEAD, KVCH), 256>>>();
    kv_reduce_kernel<<<NB * NHEAD, 256>>>();
    // 5. attn_out = z * (q @ kv)
    out_kernel<<<dim3(NB * NHEAD, NSEQ / 64), 256>>>();
    // 6. x2 = x + gamma * (attn_out @ proj_w^T + proj_b)   -> d_out
    gemm_kernel<1><<<dim3(DIMC / 128, TOK / 128), 256, SMEM_BYTES>>>(
        attn, proj_w, out, TOK, DIMC, DIMC, proj_b, x, gamma);
    // 7. xn2 = rmsnorm(x2, scale2)
    rmsnorm_kernel<<<TOK, 256>>>(out, scale2, xn);
    // 8. hdd = gelu(xn2 @ conv1_w^T + conv1_b)
    gemm_kernel<2><<<dim3(HID / 128, TOK / 128), 256, SMEM_BYTES>>>(
        xn, conv1_w, hdd, TOK, HID, DIMC, conv1_b, nullptr, nullptr);
    // 9. out = x2 + gamma * (hdd @ conv2_w^T + conv2_b)
    gemm_kernel<1><<<dim3(DIMC / 128, TOK / 128), 256, SMEM_BYTES>>>(
        hdd, conv2_w, out, TOK, DIMC, HID, conv2_b, out, gamma);
}